// round 3
// baseline (speedup 1.0000x reference)
#include <cuda_runtime.h>

#define IMG    512
#define NPIX   (IMG * IMG)
#define A_W    0.3f
#define B_W    0.7f

#define TXD    8
#define TYD    16
#define RY     2             // output rows per thread
#define CPT    8             // output cols per thread (4 packed pairs)
#define TILE_W 64            // TXD * CPT
#define TILE_H 32            // TYD * RY
#define SH_H   38            // TILE_H + 6
#define SH_W   70            // TILE_W + 6
#define S_STR  98            // S_STR/2 = 49 ≡ 1 (mod 16): rows spread across bank-pairs
#define NBX    (IMG / TILE_W)   // 8
#define NBY    (IMG / TILE_H)   // 16
#define NBLK   (NBX * NBY * 64) // 8192
#define ABSM   0x7fffffff7fffffffULL

typedef unsigned long long ull;

__device__ float g_part[NBLK];
__device__ float g_inv;
__device__ float g_mask[64 * NPIX];     // pre-normalization mask scratch
// hedge if d_out only holds the first output (verified unused; kept for safety)
__device__ float g_scr_a[64 * NPIX];
__device__ float g_scr_d[64 * NPIX];

__device__ __forceinline__ ull f2add(ull a, ull b) {
    ull r; asm("add.rn.f32x2 %0, %1, %2;" : "=l"(r) : "l"(a), "l"(b)); return r;
}
__device__ __forceinline__ ull f2fma(ull a, ull b, ull c) {
    ull r; asm("fma.rn.f32x2 %0, %1, %2, %3;" : "=l"(r) : "l"(a), "l"(b), "l"(c)); return r;
}
__device__ __forceinline__ ull fpack(float lo, float hi) {
    ull r; asm("mov.b64 %0, {%1, %2};" : "=l"(r) : "f"(lo), "f"(hi)); return r;
}
__device__ __forceinline__ void f2unpack(ull a, float& lo, float& hi) {
    asm("mov.b64 {%0, %1}, %2;" : "=f"(lo), "=f"(hi) : "l"(a));
}
// column swizzle: decollide logical cols c and c+32 (same bank-pair otherwise)
__device__ __forceinline__ int swz(int c) { return c + ((c >> 5) << 1); }

__global__ __launch_bounds__(TXD * TYD)
void stencil_kernel(const float* __restrict__ x, const float* __restrict__ w,
                    float* __restrict__ avg_out, float* __restrict__ diff_out)
{
    __shared__ __align__(16) float tile[SH_H * S_STR];
    __shared__ ull   sw2[49];
    __shared__ float red[4];

    const int tx  = threadIdx.x;
    const int ty  = threadIdx.y;
    const int tid = ty * TXD + tx;
    const int bx  = blockIdx.x * TILE_W;
    const int by  = blockIdx.y * TILE_H;
    const int b   = blockIdx.z;
    const float* xb = x + (size_t)b * NPIX;

    if (tid < 49) { float h = 0.5f * w[tid]; sw2[tid] = fpack(h, h); }

    // Fill padded tile (zero OOB) with the bank swizzle
    for (int idx = tid; idx < SH_H * SH_W; idx += TXD * TYD) {
        int r  = idx / SH_W;
        int c  = idx - r * SH_W;
        int gy = by + r - 3;
        int gx = bx + c - 3;
        float v = 0.f;
        if ((unsigned)gy < IMG && (unsigned)gx < IMG) v = __ldg(&xb[gy * IMG + gx]);
        tile[r * S_STR + swz(c)] = v;
    }
    __syncthreads();

    const int c0 = tx * CPT;     // leftmost tap column (padded coords)
    const int r0 = ty * RY;

    // Negated packed centers: output pair q covers padded cols (c0+3+2q, c0+4+2q)
    ull nxc[RY][4];
    #pragma unroll
    for (int r = 0; r < RY; ++r) {
        int base = (r0 + r + 3) * S_STR;
        #pragma unroll
        for (int q = 0; q < 4; ++q) {
            float a0 = tile[base + swz(c0 + 3 + 2 * q)];
            float a1 = tile[base + swz(c0 + 4 + 2 * q)];
            nxc[r][q] = fpack(-a0, -a1);
        }
    }

    ull mean[RY][4] = {}, diff[RY][4] = {};

    #pragma unroll
    for (int k = 0; k < RY + 6; ++k) {
        const int base = (r0 + k) * S_STR;
        ull p[13];
        float v[14];
        #pragma unroll
        for (int m = 0; m < 7; ++m) {
            p[2 * m] = *reinterpret_cast<const ull*>(&tile[base + swz(c0 + 2 * m)]);
            f2unpack(p[2 * m], v[2 * m], v[2 * m + 1]);
        }
        #pragma unroll
        for (int m = 0; m < 6; ++m) p[2 * m + 1] = fpack(v[2 * m + 1], v[2 * m + 2]);

        // packed box row-sums: rs[q] = (S_{2q}, S_{2q+1}), S_c = sum_{j=0..6} v[c+j]
        ull e0 = f2add(p[0], p[1]),  e1 = f2add(p[2], p[3]),  e2 = f2add(p[4], p[5]);
        ull e3 = f2add(p[6], p[7]),  e4 = f2add(p[8], p[9]),  e5 = f2add(p[10], p[11]);
        ull rs[4];
        rs[0] = f2add(f2add(e0, e1), f2add(e2, p[6]));
        rs[1] = f2add(f2add(e1, e2), f2add(e3, p[8]));
        rs[2] = f2add(f2add(e2, e3), f2add(e4, p[10]));
        rs[3] = f2add(f2add(e3, e4), f2add(e5, p[12]));

        #pragma unroll
        for (int r = 0; r < RY; ++r) {
            const int i = k - r;                 // tap row
            if (0 <= i && i <= 6) {
                #pragma unroll
                for (int q = 0; q < 4; ++q) mean[r][q] = f2add(mean[r][q], rs[q]);
                #pragma unroll
                for (int j = 0; j < 7; ++j) {
                    const ull w2 = sw2[i * 7 + j];           // (w/2, w/2) broadcast
                    #pragma unroll
                    for (int q = 0; q < 4; ++q) {
                        ull t = f2add(p[j + 2 * q], nxc[r][q]);
                        // relu(t)*w = (w/2)*(t+|t|), exact in fp32
                        diff[r][q] = f2fma(w2, f2add(t, t & ABSM), diff[r][q]);
                    }
                }
            }
        }
    }

    // Epilogue: avg/diff/mask stores + local ||mask||^2
    float local = 0.f;
    #pragma unroll
    for (int r = 0; r < RY; ++r) {
        float mm[8], dd[8], aa[8], kk[8];
        #pragma unroll
        for (int q = 0; q < 4; ++q) {
            f2unpack(mean[r][q], mm[2 * q], mm[2 * q + 1]);
            f2unpack(diff[r][q], dd[2 * q], dd[2 * q + 1]);
        }
        #pragma unroll
        for (int c = 0; c < 8; ++c) {
            aa[c] = __expf(mm[c] * (-1.f / 49.f));
            kk[c] = fmaf(B_W, dd[c], A_W * aa[c]);
            local += kk[c] * kk[c];
        }
        size_t o = (size_t)b * NPIX + (size_t)(by + r0 + r) * IMG + (bx + c0);
        *reinterpret_cast<float4*>(&avg_out[o])      = make_float4(aa[0], aa[1], aa[2], aa[3]);
        *reinterpret_cast<float4*>(&avg_out[o + 4])  = make_float4(aa[4], aa[5], aa[6], aa[7]);
        *reinterpret_cast<float4*>(&diff_out[o])     = make_float4(dd[0], dd[1], dd[2], dd[3]);
        *reinterpret_cast<float4*>(&diff_out[o + 4]) = make_float4(dd[4], dd[5], dd[6], dd[7]);
        *reinterpret_cast<float4*>(&g_mask[o])       = make_float4(kk[0], kk[1], kk[2], kk[3]);
        *reinterpret_cast<float4*>(&g_mask[o + 4])   = make_float4(kk[4], kk[5], kk[6], kk[7]);
    }

    // Block reduction -> plain store of partial (no atomics)
    #pragma unroll
    for (int s = 16; s > 0; s >>= 1)
        local += __shfl_down_sync(0xffffffffu, local, s);
    const int lane = tid & 31, warp = tid >> 5;
    if (lane == 0) red[warp] = local;
    __syncthreads();
    if (tid == 0) {
        float tot = red[0] + red[1] + red[2] + red[3];
        g_part[blockIdx.x + NBX * (blockIdx.y + NBY * blockIdx.z)] = tot;
    }
}

__global__ __launch_bounds__(1024)
void norm_kernel()
{
    __shared__ double red[32];
    const int tid = threadIdx.x;
    double s = 0.0;
    for (int i = tid; i < NBLK; i += 1024) s += (double)g_part[i];
    #pragma unroll
    for (int sh = 16; sh > 0; sh >>= 1)
        s += __shfl_down_sync(0xffffffffu, s, sh);
    if ((tid & 31) == 0) red[tid >> 5] = s;
    __syncthreads();
    if (tid < 32) {
        double v = red[tid];
        #pragma unroll
        for (int sh = 16; sh > 0; sh >>= 1)
            v += __shfl_down_sync(0xffffffffu, v, sh);
        if (tid == 0) g_inv = rsqrtf((float)v);
    }
}

__global__ __launch_bounds__(256)
void threshold_kernel(const float* __restrict__ x, float* __restrict__ out, int n4)
{
    int i = blockIdx.x * blockDim.x + threadIdx.x;
    if (i >= n4) return;
    const float inv = g_inv;
    float4 xv = ((const float4*)x)[i];
    float4 mv = ((const float4*)g_mask)[i];
    float4 o;
    o.x = xv.x > mv.x * inv ? xv.x : 0.f;
    o.y = xv.y > mv.y * inv ? xv.y : 0.f;
    o.z = xv.z > mv.z * inv ? xv.z : 0.f;
    o.w = xv.w > mv.w * inv ? xv.w : 0.f;
    ((float4*)out)[i] = o;
}

extern "C" void kernel_launch(void* const* d_in, const int* in_sizes, int n_in,
                              void* d_out, int out_size)
{
    const float* x = (const float*)d_in[0];
    const float* w = (const float*)d_in[1];
    float* out = (float*)d_out;

    const int N     = in_sizes[0];          // 64*512*512
    const int batch = N / NPIX;             // 64

    float* avg_ptr;
    float* diff_ptr;
    if (out_size >= 3 * N) {                // verified layout: (out, avg, diff)
        avg_ptr  = out + N;
        diff_ptr = out + 2 * N;
    } else {
        void* pa = nullptr; void* pd = nullptr;
        cudaGetSymbolAddress(&pa, g_scr_a);
        cudaGetSymbolAddress(&pd, g_scr_d);
        avg_ptr  = (float*)pa;
        diff_ptr = (float*)pd;
    }

    dim3 grid(NBX, NBY, batch);
    dim3 block(TXD, TYD);
    stencil_kernel<<<grid, block>>>(x, w, avg_ptr, diff_ptr);

    norm_kernel<<<1, 1024>>>();

    const int n4 = N / 4;
    threshold_kernel<<<(n4 + 255) / 256, 256>>>(x, out, n4);
}

// round 5
// speedup vs baseline: 1.0573x; 1.0573x over previous
#include <cuda_runtime.h>

#define IMG    512
#define NPIX   (IMG * IMG)
#define A_W    0.3f
#define B_W    0.7f

#define TXD    16
#define TYD    16
#define RY     2             // output rows per thread
#define CPT    4             // output cols per thread (2 packed pairs)
#define TILE_W 64            // TXD * CPT
#define TILE_H 32            // TYD * RY
#define SH_H   38            // TILE_H + 6
#define SH_W   70            // TILE_W + 6
#define S_STR  72            // even (keeps LDS.64 alignment); r&2 xor handles conflicts
#define NBX    (IMG / TILE_W)   // 8
#define NBY    (IMG / TILE_H)   // 16
#define NBLK   (NBX * NBY * 64) // 8192

typedef unsigned long long ull;

__device__ float g_part[NBLK];
__device__ float g_inv;
__device__ float g_mask[64 * NPIX];     // pre-normalization mask scratch
// hedge if d_out only holds the first output (verified unused; kept for safety)
__device__ float g_scr_a[64 * NPIX];
__device__ float g_scr_d[64 * NPIX];

__device__ __forceinline__ ull f2add(ull a, ull b) {
    ull r; asm("add.rn.f32x2 %0, %1, %2;" : "=l"(r) : "l"(a), "l"(b)); return r;
}
__device__ __forceinline__ ull fpack(float lo, float hi) {
    ull r; asm("mov.b64 %0, {%1, %2};" : "=l"(r) : "f"(lo), "f"(hi)); return r;
}
__device__ __forceinline__ void f2unpack(ull a, float& lo, float& hi) {
    asm("mov.b64 {%0, %1}, %2;" : "=f"(lo), "=f"(hi) : "l"(a));
}
// acc += w * relu(t), per-half FMNMX then packed FFMA2
__device__ __forceinline__ ull f2relufma(ull w, ull t, ull acc) {
    ull r;
    asm("{\n\t"
        ".reg .f32 lo, hi;\n\t"
        ".reg .b64 u;\n\t"
        "mov.b64 {lo, hi}, %2;\n\t"
        "max.f32 lo, lo, 0f00000000;\n\t"
        "max.f32 hi, hi, 0f00000000;\n\t"
        "mov.b64 u, {lo, hi};\n\t"
        "fma.rn.f32x2 %0, %1, u, %3;\n\t"
        "}" : "=l"(r) : "l"(w), "l"(t), "l"(acc));
    return r;
}

__global__ __launch_bounds__(TXD * TYD, 3)
void stencil_kernel(const float* __restrict__ x, const float* __restrict__ w,
                    float* __restrict__ avg_out, float* __restrict__ diff_out)
{
    __shared__ __align__(16) float tile[SH_H * S_STR];
    __shared__ ull   sw2[49];
    __shared__ float red[8];

    const int tx  = threadIdx.x;
    const int ty  = threadIdx.y;
    const int tid = ty * TXD + tx;
    const int bx  = blockIdx.x * TILE_W;
    const int by  = blockIdx.y * TILE_H;
    const int b   = blockIdx.z;
    const float* xb = x + (size_t)b * NPIX;

    if (tid < 49) { float h = w[tid]; sw2[tid] = fpack(h, h); }

    // Fill padded tile (zero OOB). Swizzle: physical col = c ^ (r & 2).
    for (int idx = tid; idx < SH_H * SH_W; idx += TXD * TYD) {
        int r  = idx / SH_W;
        int c  = idx - r * SH_W;
        int gy = by + r - 3;
        int gx = bx + c - 3;
        float v = 0.f;
        if ((unsigned)gy < IMG && (unsigned)gx < IMG) v = __ldg(&xb[gy * IMG + gx]);
        tile[r * S_STR + (c ^ (r & 2))] = v;
    }
    __syncthreads();

    const int c0 = tx * CPT;     // leftmost tap column (padded coords)
    const int r0 = ty * RY;

    // Negated packed centers: pair q covers padded cols (c0+3+2q, c0+4+2q)
    ull nxc[RY][2];
    #pragma unroll
    for (int r = 0; r < RY; ++r) {
        const int row = r0 + r + 3, base = row * S_STR, sz = row & 2;
        #pragma unroll
        for (int q = 0; q < 2; ++q) {
            float a0 = tile[base + ((c0 + 3 + 2 * q) ^ sz)];
            float a1 = tile[base + ((c0 + 4 + 2 * q) ^ sz)];
            nxc[r][q] = fpack(-a0, -a1);
        }
    }

    ull mean[RY][2] = {}, diff[RY][2] = {};

    #pragma unroll
    for (int k = 0; k < RY + 6; ++k) {
        const int row = r0 + k, base = row * S_STR, sz = row & 2;
        ull p[9];
        float v[10];
        #pragma unroll
        for (int m = 0; m < 5; ++m) {
            p[2 * m] = *reinterpret_cast<const ull*>(&tile[base + ((c0 + 2 * m) ^ sz)]);
            f2unpack(p[2 * m], v[2 * m], v[2 * m + 1]);
        }
        #pragma unroll
        for (int m = 0; m < 4; ++m) p[2 * m + 1] = fpack(v[2 * m + 1], v[2 * m + 2]);

        // packed box row-sums: rs0 = (S0,S1) = sum p0..p6, rs1 = (S2,S3) = sum p2..p8
        ull mid = f2add(f2add(f2add(p[2], p[3]), f2add(p[4], p[5])), p[6]);
        ull rs0 = f2add(mid, f2add(p[0], p[1]));
        ull rs1 = f2add(mid, f2add(p[7], p[8]));

        #pragma unroll
        for (int r = 0; r < RY; ++r) {
            const int i = k - r;                 // tap row
            if (0 <= i && i <= 6) {
                mean[r][0] = f2add(mean[r][0], rs0);
                mean[r][1] = f2add(mean[r][1], rs1);
                #pragma unroll
                for (int j = 0; j < 7; ++j) {
                    if (i == 3 && j == 3) continue;  // center: relu(0)=0, w=0
                    const ull w2 = sw2[i * 7 + j];
                    #pragma unroll
                    for (int q = 0; q < 2; ++q) {
                        ull t = f2add(p[j + 2 * q], nxc[r][q]);
                        diff[r][q] = f2relufma(w2, t, diff[r][q]);
                    }
                }
            }
        }
    }

    // Epilogue: avg/diff/mask stores + local ||mask||^2
    float local = 0.f;
    #pragma unroll
    for (int r = 0; r < RY; ++r) {
        float mm[4], dd[4], aa[4], kk[4];
        #pragma unroll
        for (int q = 0; q < 2; ++q) {
            f2unpack(mean[r][q], mm[2 * q], mm[2 * q + 1]);
            f2unpack(diff[r][q], dd[2 * q], dd[2 * q + 1]);
        }
        #pragma unroll
        for (int c = 0; c < 4; ++c) {
            aa[c] = __expf(mm[c] * (-1.f / 49.f));
            kk[c] = fmaf(B_W, dd[c], A_W * aa[c]);
            local += kk[c] * kk[c];
        }
        size_t o = (size_t)b * NPIX + (size_t)(by + r0 + r) * IMG + (bx + c0);
        *reinterpret_cast<float4*>(&avg_out[o])  = make_float4(aa[0], aa[1], aa[2], aa[3]);
        *reinterpret_cast<float4*>(&diff_out[o]) = make_float4(dd[0], dd[1], dd[2], dd[3]);
        *reinterpret_cast<float4*>(&g_mask[o])   = make_float4(kk[0], kk[1], kk[2], kk[3]);
    }

    // Block reduction -> plain store of partial (no atomics)
    #pragma unroll
    for (int s = 16; s > 0; s >>= 1)
        local += __shfl_down_sync(0xffffffffu, local, s);
    const int lane = tid & 31, warp = tid >> 5;
    if (lane == 0) red[warp] = local;
    __syncthreads();
    if (tid == 0) {
        float tot = 0.f;
        #pragma unroll
        for (int i = 0; i < 8; ++i) tot += red[i];
        g_part[blockIdx.x + NBX * (blockIdx.y + NBY * blockIdx.z)] = tot;
    }
}

__global__ __launch_bounds__(1024)
void norm_kernel()
{
    __shared__ double red[32];
    const int tid = threadIdx.x;
    double s = 0.0;
    for (int i = tid; i < NBLK; i += 1024) s += (double)g_part[i];
    #pragma unroll
    for (int sh = 16; sh > 0; sh >>= 1)
        s += __shfl_down_sync(0xffffffffu, s, sh);
    if ((tid & 31) == 0) red[tid >> 5] = s;
    __syncthreads();
    if (tid < 32) {
        double v = red[tid];
        #pragma unroll
        for (int sh = 16; sh > 0; sh >>= 1)
            v += __shfl_down_sync(0xffffffffu, v, sh);
        if (tid == 0) g_inv = rsqrtf((float)v);
    }
}

__global__ __launch_bounds__(256)
void threshold_kernel(const float* __restrict__ x, float* __restrict__ out, int n4)
{
    int i = blockIdx.x * blockDim.x + threadIdx.x;
    if (i >= n4) return;
    const float inv = g_inv;
    float4 xv = ((const float4*)x)[i];
    float4 mv = ((const float4*)g_mask)[i];
    float4 o;
    o.x = xv.x > mv.x * inv ? xv.x : 0.f;
    o.y = xv.y > mv.y * inv ? xv.y : 0.f;
    o.z = xv.z > mv.z * inv ? xv.z : 0.f;
    o.w = xv.w > mv.w * inv ? xv.w : 0.f;
    ((float4*)out)[i] = o;
}

extern "C" void kernel_launch(void* const* d_in, const int* in_sizes, int n_in,
                              void* d_out, int out_size)
{
    const float* x = (const float*)d_in[0];
    const float* w = (const float*)d_in[1];
    float* out = (float*)d_out;

    const int N     = in_sizes[0];          // 64*512*512
    const int batch = N / NPIX;             // 64

    float* avg_ptr;
    float* diff_ptr;
    if (out_size >= 3 * N) {                // verified layout: (out, avg, diff)
        avg_ptr  = out + N;
        diff_ptr = out + 2 * N;
    } else {
        void* pa = nullptr; void* pd = nullptr;
        cudaGetSymbolAddress(&pa, g_scr_a);
        cudaGetSymbolAddress(&pd, g_scr_d);
        avg_ptr  = (float*)pa;
        diff_ptr = (float*)pd;
    }

    dim3 grid(NBX, NBY, batch);
    dim3 block(TXD, TYD);
    stencil_kernel<<<grid, block>>>(x, w, avg_ptr, diff_ptr);

    norm_kernel<<<1, 1024>>>();

    const int n4 = N / 4;
    threshold_kernel<<<(n4 + 255) / 256, 256>>>(x, out, n4);
}

// round 9
// speedup vs baseline: 1.1127x; 1.0523x over previous
#include <cuda_runtime.h>

#define IMG    512
#define NPIX   (IMG * IMG)
#define A_W    0.3f
#define B_W    0.7f

#define TXD    16
#define TYD    16
#define RY     2             // output rows per thread
#define TILE_W 64
#define TILE_H 32            // TYD * RY
#define SH_H   38            // TILE_H + 6
#define NPAIR  38            // pair-columns: logical pair base -3..34
#define S_STR  88            // floats per shared row (≡8 mod 16: bank-safe across rows)
#define NBX    (IMG / TILE_W)   // 8
#define NBY    (IMG / TILE_H)   // 16
#define NBLK   (NBX * NBY * 64) // 8192

typedef unsigned long long ull;

__device__ float g_part[NBLK];
__device__ float g_inv;
__device__ float g_mask[64 * NPIX];     // pre-normalization mask scratch
// hedge if d_out only holds the first output (verified unused; kept for safety)
__device__ float g_scr_a[64 * NPIX];
__device__ float g_scr_d[64 * NPIX];

__device__ __forceinline__ ull f2add(ull a, ull b) {
    ull r; asm("add.rn.f32x2 %0, %1, %2;" : "=l"(r) : "l"(a), "l"(b)); return r;
}
__device__ __forceinline__ ull fpack(float lo, float hi) {
    ull r; asm("mov.b64 %0, {%1, %2};" : "=l"(r) : "f"(lo), "f"(hi)); return r;
}
__device__ __forceinline__ void f2unpack(ull a, float& lo, float& hi) {
    asm("mov.b64 {%0, %1}, %2;" : "=f"(lo), "=f"(hi) : "l"(a));
}
// acc += w * relu(t): per-half FMNMX, packed FFMA2
__device__ __forceinline__ ull f2relufma(ull w, ull t, ull acc) {
    ull r;
    asm("{\n\t"
        ".reg .f32 lo, hi;\n\t"
        ".reg .b64 u;\n\t"
        "mov.b64 {lo, hi}, %2;\n\t"
        "max.f32 lo, lo, 0f00000000;\n\t"
        "max.f32 hi, hi, 0f00000000;\n\t"
        "mov.b64 u, {lo, hi};\n\t"
        "fma.rn.f32x2 %0, %1, u, %3;\n\t"
        "}" : "=l"(r) : "l"(w), "l"(t), "l"(acc));
    return r;
}

__global__ __launch_bounds__(TXD * TYD, 4)
void stencil_kernel(const float* __restrict__ x, const float* __restrict__ w,
                    float* __restrict__ avg_out, float* __restrict__ diff_out)
{
    // Deinterleaved-pair tile: shared row r holds pairs (col p, col p+32) at
    // ull index (p+3), p = -3..34. Cols 29..34 exist twice (hi of pair p-32
    // and lo of pair p); both copies are filled below.
    __shared__ __align__(16) float tile[SH_H * S_STR];
    __shared__ ull   sw2[49];
    __shared__ float red[8];

    const int tx  = threadIdx.x;
    const int ty  = threadIdx.y;
    const int tid = ty * TXD + tx;
    const int bx  = blockIdx.x * TILE_W;
    const int by  = blockIdx.y * TILE_H;
    const int b   = blockIdx.z;
    const float* xb = x + (size_t)b * NPIX;

    if (tid < 49) { float h = w[tid]; sw2[tid] = fpack(h, h); }

    // Fill: physical slot f (0..75) in row r -> logical padded col
    // L = (f>>1) - 3 + 32*(f&1); global col gx = bx + L, row gy = by + r - 3.
    for (int idx = tid; idx < SH_H * 2 * NPAIR; idx += TXD * TYD) {
        int r = idx / (2 * NPAIR);
        int f = idx - r * (2 * NPAIR);
        int L = (f >> 1) - 3 + ((f & 1) << 5);
        int gy = by + r - 3;
        int gx = bx + L;
        float v = 0.f;
        if ((unsigned)gy < IMG && (unsigned)gx < IMG) v = __ldg(&xb[gy * IMG + gx]);
        tile[r * S_STR + f] = v;
    }
    __syncthreads();

    const int pc0 = tx;        // q0: pair covers cols (pc0, pc0+32)
    const int pc1 = tx + 16;   // q1
    const int r0  = ty * RY;

    // Negated packed centers (pair index pcq + 3 at row r0+r+3)
    ull nxc[RY][2];
    #pragma unroll
    for (int r = 0; r < RY; ++r) {
        const ull* rp = reinterpret_cast<const ull*>(&tile[(r0 + r + 3) * S_STR]);
        ull c0 = rp[pc0 + 3], c1 = rp[pc1 + 3];
        float a0, a1;
        f2unpack(c0, a0, a1); nxc[r][0] = fpack(-a0, -a1);
        f2unpack(c1, a0, a1); nxc[r][1] = fpack(-a0, -a1);
    }

    ull mean[RY][2] = {}, diff[RY][2] = {};

    #pragma unroll
    for (int k = 0; k < RY + 6; ++k) {
        const ull* rp = reinterpret_cast<const ull*>(&tile[(r0 + k) * S_STR]);

        ull P0[7], P1[7];
        #pragma unroll
        for (int m = 0; m < 7; ++m) { P0[m] = rp[pc0 + m]; P1[m] = rp[pc1 + m]; }

        ull rs0 = f2add(f2add(f2add(P0[0], P0[1]), f2add(P0[2], P0[3])),
                        f2add(f2add(P0[4], P0[5]), P0[6]));
        ull rs1 = f2add(f2add(f2add(P1[0], P1[1]), f2add(P1[2], P1[3])),
                        f2add(f2add(P1[4], P1[5]), P1[6]));

        #pragma unroll
        for (int r = 0; r < RY; ++r) {
            const int i = k - r;                 // tap row
            if (0 <= i && i <= 6) {
                mean[r][0] = f2add(mean[r][0], rs0);
                mean[r][1] = f2add(mean[r][1], rs1);
                #pragma unroll
                for (int j = 0; j < 7; ++j) {
                    if (i == 3 && j == 3) continue;   // center: relu(0)=0, w=0
                    const ull w2 = sw2[i * 7 + j];
                    diff[r][0] = f2relufma(w2, f2add(P0[j], nxc[r][0]), diff[r][0]);
                    diff[r][1] = f2relufma(w2, f2add(P1[j], nxc[r][1]), diff[r][1]);
                }
            }
        }
    }

    // Epilogue: px columns are (pc0, pc0+32, pc1, pc1+32); scalar stores are
    // coalesced per instruction (lane tx -> col tx within each group of 16).
    float local = 0.f;
    #pragma unroll
    for (int r = 0; r < RY; ++r) {
        float mm[4], dd[4];
        f2unpack(mean[r][0], mm[0], mm[1]);
        f2unpack(mean[r][1], mm[2], mm[3]);
        f2unpack(diff[r][0], dd[0], dd[1]);
        f2unpack(diff[r][1], dd[2], dd[3]);
        size_t base = (size_t)b * NPIX + (size_t)(by + r0 + r) * IMG + bx;
        const int cols[4] = { pc0, pc0 + 32, pc1, pc1 + 32 };
        #pragma unroll
        for (int c = 0; c < 4; ++c) {
            float a = __expf(mm[c] * (-1.f / 49.f));
            float kk = fmaf(B_W, dd[c], A_W * a);
            local += kk * kk;
            avg_out[base + cols[c]]  = a;
            diff_out[base + cols[c]] = dd[c];
            g_mask[base + cols[c]]   = kk;
        }
    }

    // Block reduction -> plain store of partial (no atomics)
    #pragma unroll
    for (int s = 16; s > 0; s >>= 1)
        local += __shfl_down_sync(0xffffffffu, local, s);
    const int lane = tid & 31, warp = tid >> 5;
    if (lane == 0) red[warp] = local;
    __syncthreads();
    if (tid == 0) {
        float tot = 0.f;
        #pragma unroll
        for (int i = 0; i < 8; ++i) tot += red[i];
        g_part[blockIdx.x + NBX * (blockIdx.y + NBY * blockIdx.z)] = tot;
    }
}

__global__ __launch_bounds__(1024)
void norm_kernel()
{
    __shared__ double red[32];
    const int tid = threadIdx.x;
    double s = 0.0;
    for (int i = tid; i < NBLK; i += 1024) s += (double)g_part[i];
    #pragma unroll
    for (int sh = 16; sh > 0; sh >>= 1)
        s += __shfl_down_sync(0xffffffffu, s, sh);
    if ((tid & 31) == 0) red[tid >> 5] = s;
    __syncthreads();
    if (tid < 32) {
        double v = red[tid];
        #pragma unroll
        for (int sh = 16; sh > 0; sh >>= 1)
            v += __shfl_down_sync(0xffffffffu, v, sh);
        if (tid == 0) g_inv = rsqrtf((float)v);
    }
}

__global__ __launch_bounds__(256)
void threshold_kernel(const float* __restrict__ x, float* __restrict__ out, int n4)
{
    int i = blockIdx.x * blockDim.x + threadIdx.x;
    if (i >= n4) return;
    const float inv = g_inv;
    float4 xv = ((const float4*)x)[i];
    float4 mv = ((const float4*)g_mask)[i];
    float4 o;
    o.x = xv.x > mv.x * inv ? xv.x : 0.f;
    o.y = xv.y > mv.y * inv ? xv.y : 0.f;
    o.z = xv.z > mv.z * inv ? xv.z : 0.f;
    o.w = xv.w > mv.w * inv ? xv.w : 0.f;
    ((float4*)out)[i] = o;
}

extern "C" void kernel_launch(void* const* d_in, const int* in_sizes, int n_in,
                              void* d_out, int out_size)
{
    const float* x = (const float*)d_in[0];
    const float* w = (const float*)d_in[1];
    float* out = (float*)d_out;

    const int N     = in_sizes[0];          // 64*512*512
    const int batch = N / NPIX;             // 64

    float* avg_ptr;
    float* diff_ptr;
    if (out_size >= 3 * N) {                // verified layout: (out, avg, diff)
        avg_ptr  = out + N;
        diff_ptr = out + 2 * N;
    } else {
        void* pa = nullptr; void* pd = nullptr;
        cudaGetSymbolAddress(&pa, g_scr_a);
        cudaGetSymbolAddress(&pd, g_scr_d);
        avg_ptr  = (float*)pa;
        diff_ptr = (float*)pd;
    }

    dim3 grid(NBX, NBY, batch);
    dim3 block(TXD, TYD);
    stencil_kernel<<<grid, block>>>(x, w, avg_ptr, diff_ptr);

    norm_kernel<<<1, 1024>>>();

    const int n4 = N / 4;
    threshold_kernel<<<(n4 + 255) / 256, 256>>>(x, out, n4);
}